// round 13
// baseline (speedup 1.0000x reference)
#include <cuda_runtime.h>
#include <cuda_bf16.h>
#include <cstdint>

// Problem constants
#define BB   256
#define NN   512
#define DD   128
#define C1   256          // 2*D
#define C2   128
#define BN_  131072L      // BB*NN

// Scratch (device globals; no cudaMalloc allowed)
__device__ float g_h1[BN_ * C1];
__device__ float g_h2[BN_ * C2];
__device__ float g_stats[768];
__device__ float g_aff[768];
__device__ __nv_bfloat16 g_pt_hi[(long)BB * DD * NN];   // P^T hi, [b][d][j]
__device__ __nv_bfloat16 g_pt_lo[(long)BB * DD * NN];   // P^T lo
__device__ __nv_bfloat16 g_xh[BN_ * C1];                // xcat hi (bf16 split)
__device__ __nv_bfloat16 g_xl[BN_ * C1];                // xcat lo
__device__ __nv_bfloat16 g_w1h[C1 * C1];
__device__ __nv_bfloat16 g_w1l[C1 * C1];
__device__ __nv_bfloat16 g_w2h[C2 * C1];
__device__ __nv_bfloat16 g_w2l[C2 * C1];

__device__ __forceinline__ float lrelu(float v) { return v >= 0.f ? v : 0.01f * v; }

__device__ __forceinline__ uint32_t smem_u32(const void* p) {
    uint32_t a;
    asm("{ .reg .u64 t; cvta.to.shared.u64 t, %1; cvt.u32.u64 %0, t; }" : "=r"(a) : "l"(p));
    return a;
}

__device__ __forceinline__ uint32_t prmt_hi(uint32_t a, uint32_t b) {
    uint32_t r; asm("prmt.b32 %0, %1, %2, 0x7632;" : "=r"(r) : "r"(a), "r"(b)); return r;
}
__device__ __forceinline__ uint32_t cvt_bf16x2(float x, float y) {
    uint32_t r; asm("cvt.rn.bf16x2.f32 %0, %1, %2;" : "=r"(r) : "f"(y), "f"(x)); return r;
}
__device__ __forceinline__ float trunc_bf(float x) {
    return __uint_as_float(__float_as_uint(x) & 0xFFFF0000u);
}

#define LDMX4(r, addr) \
    asm volatile("ldmatrix.sync.aligned.m8n8.x4.shared.b16 {%0,%1,%2,%3}, [%4];" \
        : "=r"((r)[0]), "=r"((r)[1]), "=r"((r)[2]), "=r"((r)[3]) : "r"(addr))

#define MMA_BF16(d, a, b0v, b1v) \
    asm volatile("mma.sync.aligned.m16n8k16.row.col.f32.bf16.bf16.f32 " \
        "{%0,%1,%2,%3}, {%4,%5,%6,%7}, {%8,%9}, {%0,%1,%2,%3};" \
        : "+f"((d)[0]), "+f"((d)[1]), "+f"((d)[2]), "+f"((d)[3]) \
        : "r"((a)[0]), "r"((a)[1]), "r"((a)[2]), "r"((a)[3]), "r"(b0v), "r"(b1v))

#define CP_ASYNC16(dst, src) \
    asm volatile("cp.async.cg.shared.global [%0], [%1], 16;" :: "r"(dst), "l"(src) : "memory")
#define CP_COMMIT() asm volatile("cp.async.commit_group;" ::: "memory")
#define CP_WAIT0()  asm volatile("cp.async.wait_group 0;" ::: "memory")
#define CP_WAIT1()  asm volatile("cp.async.wait_group 1;" ::: "memory")
#define CP_WAIT2()  asm volatile("cp.async.wait_group 2;" ::: "memory")

// 64-byte-row tile swizzle: xor bits[4:6) with row bits[1:3)
#define SW64R(row, off) ((uint32_t)(off) ^ ((((uint32_t)(row) >> 1) & 3u) << 4))

// ---- smem layouts (K=32 tiles: 128 rows x 64 B; hi at +0, lo at +8192) ----
// aggr: A stages 0,16384; B stages 32768 + (c&3)*16384
#define AG_SRS     98304
#define AG_SRINV   98816
#define AG_TOT     99328
// gemm1h: stages (c%3)*32768: A_HI+0, A_LO+8192, B_HI+16384, B_LO+24576
#define SG_SUM  98304
#define SG_SQ   98816
#define SG_TOT  99328
// gemm2h: A 0,16384; B 32768+(c&3)*16384
#define S2_AFF  98304
#define S2_SUM  100352
#define S2_SQ   100864
#define S2_TOT  101376

extern __shared__ __align__(1024) char dsm[];

// ---------------------------------------------------------------------------
// consume32: one K=32 chunk, 3-pass bf16-split HMMA, pass-major ordering.
// ---------------------------------------------------------------------------
__device__ __forceinline__ void consume32(uint32_t aHi, uint32_t bHi,
                                          int a_kb, uint32_t a_xm,
                                          int b_kb, uint32_t b_xm,
                                          float (&acc)[2][8][4]) {
    #pragma unroll
    for (int ks = 0; ks < 2; ks++) {
        const uint32_t kA = ((uint32_t)(ks * 32 + a_kb)) ^ a_xm;
        uint32_t ah[2][4], al[2][4];
        LDMX4(ah[0], aHi + kA);
        LDMX4(ah[1], aHi + 1024 + kA);
        LDMX4(al[0], aHi + 8192 + kA);
        LDMX4(al[1], aHi + 8192 + 1024 + kA);

        const uint32_t kB = ((uint32_t)(ks * 32 + b_kb)) ^ b_xm;
        #pragma unroll
        for (int nh = 0; nh < 2; nh++) {
            uint32_t bh[2][4], bl[2][4];
            LDMX4(bh[0], bHi + (uint32_t)(nh * 2048) + kB);
            LDMX4(bh[1], bHi + (uint32_t)(nh * 2048 + 1024) + kB);
            LDMX4(bl[0], bHi + 8192u + (uint32_t)(nh * 2048) + kB);
            LDMX4(bl[1], bHi + 8192u + (uint32_t)(nh * 2048 + 1024) + kB);
            // pass 1: Ah * Bh
            #pragma unroll
            for (int nf4 = 0; nf4 < 4; nf4++) {
                const int qq = nf4 >> 1, hh = (nf4 & 1) * 2;
                const int nf = nh * 4 + nf4;
                MMA_BF16(acc[0][nf], ah[0], bh[qq][hh], bh[qq][hh + 1]);
                MMA_BF16(acc[1][nf], ah[1], bh[qq][hh], bh[qq][hh + 1]);
            }
            // pass 2: Ah * Bl
            #pragma unroll
            for (int nf4 = 0; nf4 < 4; nf4++) {
                const int qq = nf4 >> 1, hh = (nf4 & 1) * 2;
                const int nf = nh * 4 + nf4;
                MMA_BF16(acc[0][nf], ah[0], bl[qq][hh], bl[qq][hh + 1]);
                MMA_BF16(acc[1][nf], ah[1], bl[qq][hh], bl[qq][hh + 1]);
            }
            // pass 3: Al * Bh
            #pragma unroll
            for (int nf4 = 0; nf4 < 4; nf4++) {
                const int qq = nf4 >> 1, hh = (nf4 & 1) * 2;
                const int nf = nh * 4 + nf4;
                MMA_BF16(acc[0][nf], al[0], bh[qq][hh], bh[qq][hh + 1]);
                MMA_BF16(acc[1][nf], al[1], bh[qq][hh], bh[qq][hh + 1]);
            }
        }
    }
}

// ---------------------------------------------------------------------------
// K-init (fused zero + P transpose/split + W split)
//  bx < 16384            : prep tile (b = bx>>6, d0 = ((bx>>4)&3)*32, j0 = (bx&15)*32)
//  16384 <= bx < 16768   : wsplit slice
//  bx == 16768           : zero stats
// ---------------------------------------------------------------------------
__global__ __launch_bounds__(256) void k_init(const float* __restrict__ P,
                                              const float* __restrict__ W1,
                                              const float* __restrict__ W2) {
    __shared__ float s[32][33];
    const int bx = blockIdx.x, t = threadIdx.x;
    if (bx < 16384) {
        int b = bx >> 6, d0 = ((bx >> 4) & 3) * 32, j0 = (bx & 15) * 32;
        {
            int jr = t >> 3, dq = (t & 7) * 4;
            float4 v = *(const float4*)(P + ((long)b * NN + j0 + jr) * DD + d0 + dq);
            s[jr][dq + 0] = v.x; s[jr][dq + 1] = v.y; s[jr][dq + 2] = v.z; s[jr][dq + 3] = v.w;
        }
        __syncthreads();
        int d = t >> 3, jq = (t & 7) * 4;
        float x0 = s[jq + 0][d], x1 = s[jq + 1][d], x2 = s[jq + 2][d], x3 = s[jq + 3][d];
        uint32_t h01 = prmt_hi(__float_as_uint(x0), __float_as_uint(x1));
        uint32_t h23 = prmt_hi(__float_as_uint(x2), __float_as_uint(x3));
        uint32_t l01 = cvt_bf16x2(x0 - trunc_bf(x0), x1 - trunc_bf(x1));
        uint32_t l23 = cvt_bf16x2(x2 - trunc_bf(x2), x3 - trunc_bf(x3));
        long off = ((long)b * DD + d0 + d) * NN + j0 + jq;
        *(uint2*)(g_pt_hi + off) = make_uint2(h01, h23);
        *(uint2*)(g_pt_lo + off) = make_uint2(l01, l23);
    } else if (bx < 16768) {
        int i = (bx - 16384) * 256 + t;
        if (i < C1 * C1) {
            float f = W1[i];
            ((unsigned short*)g_w1h)[i] = (unsigned short)(__float_as_uint(f) >> 16);
            g_w1l[i] = __float2bfloat16(f - trunc_bf(f));
        } else {
            int j = i - C1 * C1;
            float f = W2[j];
            ((unsigned short*)g_w2h)[j] = (unsigned short)(__float_as_uint(f) >> 16);
            g_w2l[j] = __float2bfloat16(f - trunc_bf(f));
        }
    } else {
        for (int q = t; q < 768; q += 256) g_stats[q] = 0.f;
    }
}

// ---------------------------------------------------------------------------
// K1: deep-pipelined bf16-split HMMA aggr. K=32 x16 chunks.
//  grid (8, 256): bx = i0*2 + edge  -> all 8 CTAs of one batch are adjacent
//  (share the same Pt tiles through L2).
//  Body order: sync -> cp -> CONSUME -> storeE -> loadE (MMA-first).
// ---------------------------------------------------------------------------
__global__ __launch_bounds__(256, 2) void k_aggr(const float* __restrict__ Ed,
                                                 const float* __restrict__ Ei) {
    const uint32_t sb = smem_u32(dsm);
    const int tid = threadIdx.x;
    const int lane = tid & 31, wid = tid >> 5;
    const int wr = wid >> 1, wc = wid & 1;
    const int b = blockIdx.y;
    const int edge = blockIdx.x & 1;
    const int i0 = (blockIdx.x >> 1) * 128;
    const float* Ebase = (edge ? Ei : Ed) + ((long)b * NN + i0) * NN;

    // ---- hoisted per-thread invariants ----
    const int e_row = tid >> 3, e_cu = tid & 7;                  // E load/store map
    const float* eP = Ebase + (long)e_row * NN + e_cu * 4;
    const uint32_t sA_off = (uint32_t)(e_row * 64) + SW64R(e_row, (e_cu >> 1) * 16)
                          + (uint32_t)((e_cu & 1) * 8);
    const int b_d = tid >> 2, b_u = tid & 3;                     // B cp map
    const __nv_bfloat16* cpsh = g_pt_hi + (long)b * DD * NN + (long)b_d * NN + b_u * 8;
    const __nv_bfloat16* cpsl = g_pt_lo + (long)b * DD * NN + (long)b_d * NN + b_u * 8;
    const uint32_t cpd = (uint32_t)(b_d * 64) + SW64R(b_d, b_u * 16);

    // consumer lane addressing
    const int a_rin = (lane & 7) + ((lane >> 3) & 1) * 8;
    const int a_kb  = (lane >> 4) * 16;
    const int a_row = wr * 32 + a_rin;
    const uint32_t a_xm = (((uint32_t)a_rin >> 1) & 3u) << 4;
    const uint32_t aRow = (uint32_t)(a_row * 64);
    const int b_nin = (lane & 7) + (lane >= 16 ? 8 : 0);
    const int b_kb  = ((lane >> 3) & 1) * 16;
    const uint32_t b_xm = (((uint32_t)b_nin >> 1) & 3u) << 4;
    const uint32_t bRow = (uint32_t)((wc * 64 + b_nin) * 64);

    float acc[2][8][4];
    #pragma unroll
    for (int mf = 0; mf < 2; mf++)
        #pragma unroll
        for (int nf = 0; nf < 8; nf++)
            #pragma unroll
            for (int q = 0; q < 4; q++) acc[mf][nf][q] = 0.f;

    float rs[4];
    #pragma unroll
    for (int i = 0; i < 4; i++) rs[i] = 0.f;
    float4 v[4];

    #define AGGR_CPB(c) do { \
        uint32_t _st = sb + 32768u + (uint32_t)(((c) & 3) * 16384); \
        _Pragma("unroll") \
        for (int _it = 0; _it < 2; _it++) { \
            uint32_t _dst = _st + cpd + (uint32_t)(_it * 4096); \
            CP_ASYNC16(_dst,         cpsh + (long)_it * 64 * NN + (c) * 32); \
            CP_ASYNC16(_dst + 8192u, cpsl + (long)_it * 64 * NN + (c) * 32); \
        } \
        CP_COMMIT(); \
    } while (0)

    #define AGGR_LOADE(c) do { \
        _Pragma("unroll") \
        for (int _it = 0; _it < 4; _it++) \
            v[_it] = *(const float4*)(eP + (long)_it * 32 * NN + (c) * 32); \
    } while (0)

    #define AGGR_STOREE(c) do { \
        uint32_t _soff = (uint32_t)(((c) & 1) * 16384) + sA_off; \
        int _jb = (c) * 32 + e_cu * 4; \
        _Pragma("unroll") \
        for (int _it = 0; _it < 4; _it++) { \
            int _irow = i0 + e_row + _it * 32; \
            float4 _a = v[_it]; \
            if (_jb + 0 == _irow) _a.x = 0.f; \
            if (_jb + 1 == _irow) _a.y = 0.f; \
            if (_jb + 2 == _irow) _a.z = 0.f; \
            if (_jb + 3 == _irow) _a.w = 0.f; \
            rs[_it] += _a.x + _a.y + _a.z + _a.w; \
            uint32_t _h0 = prmt_hi(__float_as_uint(_a.x), __float_as_uint(_a.y)); \
            uint32_t _h1 = prmt_hi(__float_as_uint(_a.z), __float_as_uint(_a.w)); \
            uint32_t _l0 = cvt_bf16x2(_a.x - trunc_bf(_a.x), _a.y - trunc_bf(_a.y)); \
            uint32_t _l1 = cvt_bf16x2(_a.z - trunc_bf(_a.z), _a.w - trunc_bf(_a.w)); \
            uint32_t _off = _soff + (uint32_t)(_it * 2048); \
            *(uint2*)(dsm + _off)        = make_uint2(_h0, _h1); \
            *(uint2*)(dsm + 8192 + _off) = make_uint2(_l0, _l1); \
        } \
    } while (0)

    // prologue
    AGGR_CPB(0); AGGR_CPB(1); AGGR_CPB(2);
    AGGR_LOADE(0);
    AGGR_STOREE(0);
    AGGR_LOADE(1);

    #pragma unroll 4
    for (int c = 0; c < 16; c++) {
        if (c < 14) { CP_WAIT2(); } else if (c == 14) { CP_WAIT1(); } else { CP_WAIT0(); }
        __syncthreads();
        if (c < 13) AGGR_CPB(c + 3);
        uint32_t aHi = sb + (uint32_t)((c & 1) * 16384) + aRow;
        uint32_t bHi = sb + 32768u + (uint32_t)((c & 3) * 16384) + bRow;
        consume32(aHi, bHi, a_kb, a_xm, b_kb, b_xm, acc);
        if (c < 15) AGGR_STOREE(c + 1);
        if (c < 14) AGGR_LOADE(c + 2);
    }

    // rowsum reduce: 8 consecutive threads share a row
    __syncthreads();
    float* srs = (float*)(dsm + AG_SRS);
    #pragma unroll
    for (int it = 0; it < 4; it++) {
        float s = rs[it];
        #pragma unroll
        for (int m = 1; m <= 4; m <<= 1) s += __shfl_xor_sync(0xffffffffu, s, m);
        if ((lane & 7) == 0) srs[(tid >> 3) + it * 32] = s;
    }
    __syncthreads();
    float* rinv = (float*)(dsm + AG_SRINV);
    if (tid < 128) rinv[tid] = 1.f / fmaxf(srs[tid], 1e-12f);
    __syncthreads();

    // epilogue: scale + split bf16 store
    #pragma unroll
    for (int mf = 0; mf < 2; mf++) {
        const int lr0 = wr * 32 + mf * 16 + (lane >> 2);
        const float inv0 = rinv[lr0], inv1 = rinv[lr0 + 8];
        long idx0 = ((long)(b * NN + i0 + lr0)) * C1 + edge * 128 + wc * 64 + 2 * (lane & 3);
        long idx1 = idx0 + 8L * C1;
        #pragma unroll
        for (int nf = 0; nf < 8; nf++) {
            float x0 = acc[mf][nf][0] * inv0, x1 = acc[mf][nf][1] * inv0;
            float y0 = acc[mf][nf][2] * inv1, y1 = acc[mf][nf][3] * inv1;
            *(uint32_t*)(g_xh + idx0 + nf * 8) = prmt_hi(__float_as_uint(x0), __float_as_uint(x1));
            *(uint32_t*)(g_xl + idx0 + nf * 8) = cvt_bf16x2(x0 - trunc_bf(x0), x1 - trunc_bf(x1));
            *(uint32_t*)(g_xh + idx1 + nf * 8) = prmt_hi(__float_as_uint(y0), __float_as_uint(y1));
            *(uint32_t*)(g_xl + idx1 + nf * 8) = cvt_bf16x2(y0 - trunc_bf(y0), y1 - trunc_bf(y1));
        }
    }
}

// ---------------------------------------------------------------------------
// K2: HMMA gemm1 (3-stage all-cp.async pipeline, K=32 x8 chunks) + BN stats
// ---------------------------------------------------------------------------
__global__ __launch_bounds__(256, 2) void k_gemm1h() {
    const uint32_t sb = smem_u32(dsm);
    const int tid = threadIdx.x;
    const int lane = tid & 31, wid = tid >> 5;
    const int wr = wid >> 1, wc = wid & 1;
    const long m0 = (long)blockIdx.y * 128;
    const int n0 = blockIdx.x * 128;

    const int g_r = tid >> 2, g_u = tid & 3;
    const __nv_bfloat16* sxh = g_xh + (m0 + g_r) * C1 + g_u * 8;
    const __nv_bfloat16* sxl = g_xl + (m0 + g_r) * C1 + g_u * 8;
    const __nv_bfloat16* swh = g_w1h + (long)(n0 + g_r) * C1 + g_u * 8;
    const __nv_bfloat16* swl = g_w1l + (long)(n0 + g_r) * C1 + g_u * 8;
    const uint32_t cpd = (uint32_t)(g_r * 64) + SW64R(g_r, g_u * 16);

    const int a_rin = (lane & 7) + ((lane >> 3) & 1) * 8;
    const int a_kb  = (lane >> 4) * 16;
    const int a_row = wr * 32 + a_rin;
    const uint32_t a_xm = (((uint32_t)a_rin >> 1) & 3u) << 4;
    const uint32_t aRow = (uint32_t)(a_row * 64);
    const int b_nin = (lane & 7) + (lane >= 16 ? 8 : 0);
    const int b_kb  = ((lane >> 3) & 1) * 16;
    const uint32_t b_xm = (((uint32_t)b_nin >> 1) & 3u) << 4;
    const uint32_t bRow = (uint32_t)((wc * 64 + b_nin) * 64);

    float* ssum = (float*)(dsm + SG_SUM);
    float* ssq  = (float*)(dsm + SG_SQ);
    if (tid < 128) { ssum[tid] = 0.f; ssq[tid] = 0.f; }

    float acc[2][8][4];
    #pragma unroll
    for (int mf = 0; mf < 2; mf++)
        #pragma unroll
        for (int nf = 0; nf < 8; nf++)
            #pragma unroll
            for (int q = 0; q < 4; q++) acc[mf][nf][q] = 0.f;

    #define G1_CP(c) do { \
        uint32_t _st = sb + (uint32_t)(((c) % 3) * 32768); \
        _Pragma("unroll") \
        for (int _it = 0; _it < 2; _it++) { \
            uint32_t _dst = _st + cpd + (uint32_t)(_it * 4096); \
            CP_ASYNC16(_dst,          sxh + (long)_it * 64 * C1 + (c) * 32); \
            CP_ASYNC16(_dst + 8192u,  sxl + (long)_it * 64 * C1 + (c) * 32); \
            CP_ASYNC16(_dst + 16384u, swh + (long)_it * 64 * C1 + (c) * 32); \
            CP_ASYNC16(_dst + 24576u, swl + (long)_it * 64 * C1 + (c) * 32); \
        } \
        CP_COMMIT(); \
    } while (0)

    G1_CP(0);
    G1_CP(1);
    #pragma unroll
    for (int c = 0; c < 8; c++) {
        if (c < 7) { CP_WAIT1(); } else { CP_WAIT0(); }
        __syncthreads();
        if (c < 6) G1_CP(c + 2);
        uint32_t st = sb + (uint32_t)((c % 3) * 32768);
        consume32(st + aRow, st + 16384u + bRow, a_kb, a_xm, b_kb, b_xm, acc);
    }

    // store h1 + stats
    #pragma unroll
    for (int mf = 0; mf < 2; mf++) {
        const int lr0 = wr * 32 + mf * 16 + (lane >> 2);
        float* d0 = g_h1 + (m0 + lr0) * C1 + n0 + wc * 64 + 2 * (lane & 3);
        float* d1 = d0 + 8L * C1;
        #pragma unroll
        for (int nf = 0; nf < 8; nf++) {
            *(float2*)(d0 + nf * 8) = make_float2(acc[mf][nf][0], acc[mf][nf][1]);
            *(float2*)(d1 + nf * 8) = make_float2(acc[mf][nf][2], acc[mf][nf][3]);
        }
    }
    #pragma unroll
    for (int nf = 0; nf < 8; nf++) {
        #pragma unroll
        for (int par = 0; par < 2; par++) {
            float v0 = acc[0][nf][par], v1 = acc[0][nf][par + 2];
            float v2 = acc[1][nf][par], v3 = acc[1][nf][par + 2];
            float s = v0 + v1 + v2 + v3;
            float q = v0 * v0 + v1 * v1 + v2 * v2 + v3 * v3;
            #pragma unroll
            for (int m = 4; m <= 16; m <<= 1) {
                s += __shfl_xor_sync(0xffffffffu, s, m);
                q += __shfl_xor_sync(0xffffffffu, q, m);
            }
            if (lane < 4) {
                int ch = wc * 64 + nf * 8 + 2 * lane + par;
                atomicAdd(&ssum[ch], s);
                atomicAdd(&ssq[ch], q);
            }
        }
    }
    __syncthreads();
    if (tid < 128) {
        atomicAdd(&g_stats[n0 + tid], ssum[tid]);
        atomicAdd(&g_stats[256 + n0 + tid], ssq[tid]);
    }
}

// ---------------------------------------------------------------------------
__global__ void k_bnaff(const float* __restrict__ g, const float* __restrict__ b,
                        int C, int statoff, int affoff) {
    int o = threadIdx.x;
    if (o < C) {
        const float inv_cnt = 1.f / 131072.f;
        float mean = g_stats[statoff + o] * inv_cnt;
        float var  = g_stats[statoff + C + o] * inv_cnt - mean * mean;
        float sc = g[o] * rsqrtf(var + 1e-5f);
        g_aff[affoff + o]     = sc;
        g_aff[affoff + C + o] = b[o] - mean * sc;
    }
}

// ---------------------------------------------------------------------------
// K4: HMMA gemm2 (A 2-stage affine+split, B 4-stage cp.async, K=32 x8)
//  MMA-first body order.
// ---------------------------------------------------------------------------
__global__ __launch_bounds__(256, 2) void k_gemm2h() {
    const uint32_t sb = smem_u32(dsm);
    const int tid = threadIdx.x;
    const int lane = tid & 31, wid = tid >> 5;
    const int wr = wid >> 1, wc = wid & 1;
    const long m0 = (long)blockIdx.x * 128;

    const int e_row = tid >> 3, e_cu = tid & 7;
    const float* aP = g_h1 + (m0 + e_row) * C1 + e_cu * 4;
    const uint32_t sA_off = (uint32_t)(e_row * 64) + SW64R(e_row, (e_cu >> 1) * 16)
                          + (uint32_t)((e_cu & 1) * 8);
    const int b_d = tid >> 2, b_u = tid & 3;
    const __nv_bfloat16* cpsh = g_w2h + (long)b_d * C1 + b_u * 8;
    const __nv_bfloat16* cpsl = g_w2l + (long)b_d * C1 + b_u * 8;
    const uint32_t cpd = (uint32_t)(b_d * 64) + SW64R(b_d, b_u * 16);

    const int a_rin = (lane & 7) + ((lane >> 3) & 1) * 8;
    const int a_kb  = (lane >> 4) * 16;
    const int a_row = wr * 32 + a_rin;
    const uint32_t a_xm = (((uint32_t)a_rin >> 1) & 3u) << 4;
    const uint32_t aRow = (uint32_t)(a_row * 64);
    const int b_nin = (lane & 7) + (lane >= 16 ? 8 : 0);
    const int b_kb  = ((lane >> 3) & 1) * 16;
    const uint32_t b_xm = (((uint32_t)b_nin >> 1) & 3u) << 4;
    const uint32_t bRow = (uint32_t)((wc * 64 + b_nin) * 64);

    float* saff0 = (float*)(dsm + S2_AFF);
    float* saff1 = saff0 + 256;
    float* ssum  = (float*)(dsm + S2_SUM);
    float* ssq   = (float*)(dsm + S2_SQ);
    saff0[tid] = g_aff[tid];
    saff1[tid] = g_aff[256 + tid];
    if (tid < 128) { ssum[tid] = 0.f; ssq[tid] = 0.f; }
    __syncthreads();

    float acc[2][8][4];
    #pragma unroll
    for (int mf = 0; mf < 2; mf++)
        #pragma unroll
        for (int nf = 0; nf < 8; nf++)
            #pragma unroll
            for (int q = 0; q < 4; q++) acc[mf][nf][q] = 0.f;

    float4 v[4];

    #define G2_CPB(c) do { \
        uint32_t _st = sb + 32768u + (uint32_t)(((c) & 3) * 16384); \
        _Pragma("unroll") \
        for (int _it = 0; _it < 2; _it++) { \
            uint32_t _dst = _st + cpd + (uint32_t)(_it * 4096); \
            CP_ASYNC16(_dst,         cpsh + (long)_it * 64 * C1 + (c) * 32); \
            CP_ASYNC16(_dst + 8192u, cpsl + (long)_it * 64 * C1 + (c) * 32); \
        } \
        CP_COMMIT(); \
    } while (0)

    #define G2_LOADA(c) do { \
        _Pragma("unroll") \
        for (int _it = 0; _it < 4; _it++) \
            v[_it] = *(const float4*)(aP + (long)_it * 32 * C1 + (c) * 32); \
    } while (0)

    #define G2_STOREA(c) do { \
        uint32_t _soff = (uint32_t)(((c) & 1) * 16384) + sA_off; \
        int _ch = (c) * 32 + e_cu * 4; \
        _Pragma("unroll") \
        for (int _it = 0; _it < 4; _it++) { \
            float4 _a = v[_it]; \
            _a.x = lrelu(saff0[_ch + 0] * _a.x + saff1[_ch + 0]); \
            _a.y = lrelu(saff0[_ch + 1] * _a.y + saff1[_ch + 1]); \
            _a.z = lrelu(saff0[_ch + 2] * _a.z + saff1[_ch + 2]); \
            _a.w = lrelu(saff0[_ch + 3] * _a.w + saff1[_ch + 3]); \
            uint32_t _h0 = prmt_hi(__float_as_uint(_a.x), __float_as_uint(_a.y)); \
            uint32_t _h1 = prmt_hi(__float_as_uint(_a.z), __float_as_uint(_a.w)); \
            uint32_t _l0 = cvt_bf16x2(_a.x - trunc_bf(_a.x), _a.y - trunc_bf(_a.y)); \
            uint32_t _l1 = cvt_bf16x2(_a.z - trunc_bf(_a.z), _a.w - trunc_bf(_a.w)); \
            uint32_t _off = _soff + (uint32_t)(_it * 2048); \
            *(uint2*)(dsm + _off)        = make_uint2(_h0, _h1); \
            *(uint2*)(dsm + 8192 + _off) = make_uint2(_l0, _l1); \
        } \
    } while (0)

    G2_CPB(0); G2_CPB(1); G2_CPB(2);
    G2_LOADA(0);
    G2_STOREA(0);
    G2_LOADA(1);

    #pragma unroll
    for (int c = 0; c < 8; c++) {
        if (c < 6) { CP_WAIT2(); } else if (c == 6) { CP_WAIT1(); } else { CP_WAIT0(); }
        __syncthreads();
        if (c < 5) G2_CPB(c + 3);
        uint32_t aHi = sb + (uint32_t)((c & 1) * 16384) + aRow;
        uint32_t bHi = sb + 32768u + (uint32_t)((c & 3) * 16384) + bRow;
        consume32(aHi, bHi, a_kb, a_xm, b_kb, b_xm, acc);
        if (c < 7) G2_STOREA(c + 1);
        if (c < 6) G2_LOADA(c + 2);
    }

    // store h2 + stats
    #pragma unroll
    for (int mf = 0; mf < 2; mf++) {
        const int lr0 = wr * 32 + mf * 16 + (lane >> 2);
        float* d0 = g_h2 + (m0 + lr0) * C2 + wc * 64 + 2 * (lane & 3);
        float* d1 = d0 + 8L * C2;
        #pragma unroll
        for (int nf = 0; nf < 8; nf++) {
            *(float2*)(d0 + nf * 8) = make_float2(acc[mf][nf][0], acc[mf][nf][1]);
            *(float2*)(d1 + nf * 8) = make_float2(acc[mf][nf][2], acc[mf][nf][3]);
        }
    }
    #pragma unroll
    for (int nf = 0; nf < 8; nf++) {
        #pragma unroll
        for (int par = 0; par < 2; par++) {
            float v0 = acc[0][nf][par], v1 = acc[0][nf][par + 2];
            float v2 = acc[1][nf][par], v3 = acc[1][nf][par + 2];
            float s = v0 + v1 + v2 + v3;
            float q = v0 * v0 + v1 * v1 + v2 * v2 + v3 * v3;
            #pragma unroll
            for (int m = 4; m <= 16; m <<= 1) {
                s += __shfl_xor_sync(0xffffffffu, s, m);
                q += __shfl_xor_sync(0xffffffffu, q, m);
            }
            if (lane < 4) {
                int ch = wc * 64 + nf * 8 + 2 * lane + par;
                atomicAdd(&ssum[ch], s);
                atomicAdd(&ssq[ch], q);
            }
        }
    }
    __syncthreads();
    if (tid < 128) {
        atomicAdd(&g_stats[512 + tid], ssum[tid]);
        atomicAdd(&g_stats[640 + tid], ssq[tid]);
    }
}

// ---------------------------------------------------------------------------
__global__ __launch_bounds__(256) void k_final(float* __restrict__ out) {
    long idx = ((long)blockIdx.x * blockDim.x + threadIdx.x);
    long e = idx * 4;
    int ch = (int)(e & 127);
    float4 v = *(const float4*)&g_h2[e];
    v.x = lrelu(g_aff[512 + ch + 0] * v.x + g_aff[640 + ch + 0]);
    v.y = lrelu(g_aff[512 + ch + 1] * v.y + g_aff[640 + ch + 1]);
    v.z = lrelu(g_aff[512 + ch + 2] * v.z + g_aff[640 + ch + 2]);
    v.w = lrelu(g_aff[512 + ch + 3] * v.w + g_aff[640 + ch + 3]);
    *(float4*)&out[e] = v;
}

// ---------------------------------------------------------------------------
extern "C" void kernel_launch(void* const* d_in, const int* in_sizes, int n_in,
                              void* d_out, int out_size) {
    const float* Ed = (const float*)d_in[0];
    const float* Ei = (const float*)d_in[1];
    const float* P  = (const float*)d_in[2];
    const float* W1 = (const float*)d_in[3];
    const float* g1 = (const float*)d_in[4];
    const float* b1 = (const float*)d_in[5];
    const float* W2 = (const float*)d_in[6];
    const float* g2 = (const float*)d_in[7];
    const float* b2 = (const float*)d_in[8];
    float* out = (float*)d_out;

    cudaFuncSetAttribute((const void*)k_aggr,
                         cudaFuncAttributeMaxDynamicSharedMemorySize, AG_TOT);
    cudaFuncSetAttribute((const void*)k_gemm1h,
                         cudaFuncAttributeMaxDynamicSharedMemorySize, SG_TOT);
    cudaFuncSetAttribute((const void*)k_gemm2h,
                         cudaFuncAttributeMaxDynamicSharedMemorySize, S2_TOT);

    k_init<<<16769, 256>>>(P, W1, W2);
    k_aggr<<<dim3(8, 256), 256, AG_TOT>>>(Ed, Ei);
    k_gemm1h<<<dim3(2, 1024), 256, SG_TOT>>>();
    k_bnaff<<<1, 256>>>(g1, b1, 256, 0, 0);
    k_gemm2h<<<1024, 256, S2_TOT>>>();
    k_bnaff<<<1, 128>>>(g2, b2, 128, 512, 512);
    k_final<<<(int)(BN_ * C2 / 4 / 256), 256>>>(out);
}

// round 14
// speedup vs baseline: 1.0585x; 1.0585x over previous
#include <cuda_runtime.h>
#include <cuda_bf16.h>
#include <cstdint>

// Problem constants
#define BB   256
#define NN   512
#define DD   128
#define C1   256          // 2*D
#define C2   128
#define BN_  131072L      // BB*NN

// Scratch (device globals; no cudaMalloc allowed)
__device__ float g_h1[BN_ * C1];
__device__ float g_h2[BN_ * C2];
__device__ float g_stats[768];
__device__ float g_aff[768];
__device__ __nv_bfloat16 g_pt_hi[(long)BB * DD * NN];   // P^T hi, [b][d][j]
__device__ __nv_bfloat16 g_pt_lo[(long)BB * DD * NN];   // P^T lo
__device__ __nv_bfloat16 g_xh[BN_ * C1];                // xcat hi (bf16 split)
__device__ __nv_bfloat16 g_xl[BN_ * C1];                // xcat lo
__device__ __nv_bfloat16 g_w1h[C1 * C1];
__device__ __nv_bfloat16 g_w1l[C1 * C1];
__device__ __nv_bfloat16 g_w2h[C2 * C1];
__device__ __nv_bfloat16 g_w2l[C2 * C1];

__device__ __forceinline__ float lrelu(float v) { return v >= 0.f ? v : 0.01f * v; }

__device__ __forceinline__ uint32_t smem_u32(const void* p) {
    uint32_t a;
    asm("{ .reg .u64 t; cvta.to.shared.u64 t, %1; cvt.u32.u64 %0, t; }" : "=r"(a) : "l"(p));
    return a;
}

__device__ __forceinline__ uint32_t prmt_hi(uint32_t a, uint32_t b) {
    uint32_t r; asm("prmt.b32 %0, %1, %2, 0x7632;" : "=r"(r) : "r"(a), "r"(b)); return r;
}
__device__ __forceinline__ uint32_t cvt_bf16x2(float x, float y) {
    uint32_t r; asm("cvt.rn.bf16x2.f32 %0, %1, %2;" : "=r"(r) : "f"(y), "f"(x)); return r;
}
__device__ __forceinline__ float trunc_bf(float x) {
    return __uint_as_float(__float_as_uint(x) & 0xFFFF0000u);
}

#define LDMX4(r, addr) \
    asm volatile("ldmatrix.sync.aligned.m8n8.x4.shared.b16 {%0,%1,%2,%3}, [%4];" \
        : "=r"((r)[0]), "=r"((r)[1]), "=r"((r)[2]), "=r"((r)[3]) : "r"(addr))

#define MMA_BF16(d, a, b0v, b1v) \
    asm volatile("mma.sync.aligned.m16n8k16.row.col.f32.bf16.bf16.f32 " \
        "{%0,%1,%2,%3}, {%4,%5,%6,%7}, {%8,%9}, {%0,%1,%2,%3};" \
        : "+f"((d)[0]), "+f"((d)[1]), "+f"((d)[2]), "+f"((d)[3]) \
        : "r"((a)[0]), "r"((a)[1]), "r"((a)[2]), "r"((a)[3]), "r"(b0v), "r"(b1v))

#define CP_ASYNC16(dst, src) \
    asm volatile("cp.async.cg.shared.global [%0], [%1], 16;" :: "r"(dst), "l"(src) : "memory")
#define CP_COMMIT() asm volatile("cp.async.commit_group;" ::: "memory")
#define CP_WAIT0()  asm volatile("cp.async.wait_group 0;" ::: "memory")
#define CP_WAIT1()  asm volatile("cp.async.wait_group 1;" ::: "memory")
#define CP_WAIT2()  asm volatile("cp.async.wait_group 2;" ::: "memory")

// 64-byte-row tile swizzle: xor bits[4:6) with row bits[1:3)
#define SW64R(row, off) ((uint32_t)(off) ^ ((((uint32_t)(row) >> 1) & 3u) << 4))

// ---- smem layouts (K=32 tiles: 128 rows x 64 B; hi at +0, lo at +8192) ----
// aggr: A stages 0,16384; B stages 32768 + (c&3)*16384
#define AG_SRS     98304
#define AG_SRINV   98816
#define AG_TOT     99328
// gemm1h: stages (c%3)*32768: A_HI+0, A_LO+8192, B_HI+16384, B_LO+24576
#define SG_SUM  98304
#define SG_SQ   98816
#define SG_TOT  99328
// gemm2h: A 0,16384; B 32768+(c&3)*16384
#define S2_AFF  98304
#define S2_SUM  100352
#define S2_SQ   100864
#define S2_TOT  101376

extern __shared__ __align__(1024) char dsm[];

// ---------------------------------------------------------------------------
// consume32: one K=32 chunk, 3-pass bf16-split HMMA, pass-major ordering.
// ---------------------------------------------------------------------------
__device__ __forceinline__ void consume32(uint32_t aHi, uint32_t bHi,
                                          int a_kb, uint32_t a_xm,
                                          int b_kb, uint32_t b_xm,
                                          float (&acc)[2][8][4]) {
    #pragma unroll
    for (int ks = 0; ks < 2; ks++) {
        const uint32_t kA = ((uint32_t)(ks * 32 + a_kb)) ^ a_xm;
        uint32_t ah[2][4], al[2][4];
        LDMX4(ah[0], aHi + kA);
        LDMX4(ah[1], aHi + 1024 + kA);
        LDMX4(al[0], aHi + 8192 + kA);
        LDMX4(al[1], aHi + 8192 + 1024 + kA);

        const uint32_t kB = ((uint32_t)(ks * 32 + b_kb)) ^ b_xm;
        #pragma unroll
        for (int nh = 0; nh < 2; nh++) {
            uint32_t bh[2][4], bl[2][4];
            LDMX4(bh[0], bHi + (uint32_t)(nh * 2048) + kB);
            LDMX4(bh[1], bHi + (uint32_t)(nh * 2048 + 1024) + kB);
            LDMX4(bl[0], bHi + 8192u + (uint32_t)(nh * 2048) + kB);
            LDMX4(bl[1], bHi + 8192u + (uint32_t)(nh * 2048 + 1024) + kB);
            // pass 1: Ah * Bh
            #pragma unroll
            for (int nf4 = 0; nf4 < 4; nf4++) {
                const int qq = nf4 >> 1, hh = (nf4 & 1) * 2;
                const int nf = nh * 4 + nf4;
                MMA_BF16(acc[0][nf], ah[0], bh[qq][hh], bh[qq][hh + 1]);
                MMA_BF16(acc[1][nf], ah[1], bh[qq][hh], bh[qq][hh + 1]);
            }
            // pass 2: Ah * Bl
            #pragma unroll
            for (int nf4 = 0; nf4 < 4; nf4++) {
                const int qq = nf4 >> 1, hh = (nf4 & 1) * 2;
                const int nf = nh * 4 + nf4;
                MMA_BF16(acc[0][nf], ah[0], bl[qq][hh], bl[qq][hh + 1]);
                MMA_BF16(acc[1][nf], ah[1], bl[qq][hh], bl[qq][hh + 1]);
            }
            // pass 3: Al * Bh
            #pragma unroll
            for (int nf4 = 0; nf4 < 4; nf4++) {
                const int qq = nf4 >> 1, hh = (nf4 & 1) * 2;
                const int nf = nh * 4 + nf4;
                MMA_BF16(acc[0][nf], al[0], bh[qq][hh], bh[qq][hh + 1]);
                MMA_BF16(acc[1][nf], al[1], bh[qq][hh], bh[qq][hh + 1]);
            }
        }
    }
}

// ---------------------------------------------------------------------------
// K-init (fused zero + P transpose/split + W split)
// ---------------------------------------------------------------------------
__global__ __launch_bounds__(256) void k_init(const float* __restrict__ P,
                                              const float* __restrict__ W1,
                                              const float* __restrict__ W2) {
    __shared__ float s[32][33];
    const int bx = blockIdx.x, t = threadIdx.x;
    if (bx < 16384) {
        int b = bx >> 6, d0 = ((bx >> 4) & 3) * 32, j0 = (bx & 15) * 32;
        {
            int jr = t >> 3, dq = (t & 7) * 4;
            float4 v = *(const float4*)(P + ((long)b * NN + j0 + jr) * DD + d0 + dq);
            s[jr][dq + 0] = v.x; s[jr][dq + 1] = v.y; s[jr][dq + 2] = v.z; s[jr][dq + 3] = v.w;
        }
        __syncthreads();
        int d = t >> 3, jq = (t & 7) * 4;
        float x0 = s[jq + 0][d], x1 = s[jq + 1][d], x2 = s[jq + 2][d], x3 = s[jq + 3][d];
        uint32_t h01 = prmt_hi(__float_as_uint(x0), __float_as_uint(x1));
        uint32_t h23 = prmt_hi(__float_as_uint(x2), __float_as_uint(x3));
        uint32_t l01 = cvt_bf16x2(x0 - trunc_bf(x0), x1 - trunc_bf(x1));
        uint32_t l23 = cvt_bf16x2(x2 - trunc_bf(x2), x3 - trunc_bf(x3));
        long off = ((long)b * DD + d0 + d) * NN + j0 + jq;
        *(uint2*)(g_pt_hi + off) = make_uint2(h01, h23);
        *(uint2*)(g_pt_lo + off) = make_uint2(l01, l23);
    } else if (bx < 16768) {
        int i = (bx - 16384) * 256 + t;
        if (i < C1 * C1) {
            float f = W1[i];
            ((unsigned short*)g_w1h)[i] = (unsigned short)(__float_as_uint(f) >> 16);
            g_w1l[i] = __float2bfloat16(f - trunc_bf(f));
        } else {
            int j = i - C1 * C1;
            float f = W2[j];
            ((unsigned short*)g_w2h)[j] = (unsigned short)(__float_as_uint(f) >> 16);
            g_w2l[j] = __float2bfloat16(f - trunc_bf(f));
        }
    } else {
        for (int q = t; q < 768; q += 256) g_stats[q] = 0.f;
    }
}

// ---------------------------------------------------------------------------
// K1: deep-pipelined bf16-split HMMA aggr. K=32 x16 chunks.
//  A 2-stage STS (mask+split), B 4-stage cp.async (3-chunk lookahead).
//  Body: wait -> sync -> cp(c+3) -> storeE(c+1) -> loadE(c+2) -> consume(c)
//  (loads issued BEFORE consume so DRAM latency hides under MMA — R12 proven)
// ---------------------------------------------------------------------------
__global__ __launch_bounds__(256, 2) void k_aggr(const float* __restrict__ Ed,
                                                 const float* __restrict__ Ei) {
    const uint32_t sb = smem_u32(dsm);
    const int tid = threadIdx.x;
    const int lane = tid & 31, wid = tid >> 5;
    const int wr = wid >> 1, wc = wid & 1;
    const int b = blockIdx.y, i0 = blockIdx.x * 128, edge = blockIdx.z;
    const float* Ebase = (edge ? Ei : Ed) + ((long)b * NN + i0) * NN;

    // ---- hoisted per-thread invariants ----
    const int e_row = tid >> 3, e_cu = tid & 7;                  // E load/store map
    const float* eP = Ebase + (long)e_row * NN + e_cu * 4;
    const uint32_t sA_off = (uint32_t)(e_row * 64) + SW64R(e_row, (e_cu >> 1) * 16)
                          + (uint32_t)((e_cu & 1) * 8);
    const int b_d = tid >> 2, b_u = tid & 3;                     // B cp map
    const __nv_bfloat16* cpsh = g_pt_hi + (long)b * DD * NN + (long)b_d * NN + b_u * 8;
    const __nv_bfloat16* cpsl = g_pt_lo + (long)b * DD * NN + (long)b_d * NN + b_u * 8;
    const uint32_t cpd = (uint32_t)(b_d * 64) + SW64R(b_d, b_u * 16);

    // consumer lane addressing
    const int a_rin = (lane & 7) + ((lane >> 3) & 1) * 8;
    const int a_kb  = (lane >> 4) * 16;
    const int a_row = wr * 32 + a_rin;
    const uint32_t a_xm = (((uint32_t)a_rin >> 1) & 3u) << 4;
    const uint32_t aRow = (uint32_t)(a_row * 64);
    const int b_nin = (lane & 7) + (lane >= 16 ? 8 : 0);
    const int b_kb  = ((lane >> 3) & 1) * 16;
    const uint32_t b_xm = (((uint32_t)b_nin >> 1) & 3u) << 4;
    const uint32_t bRow = (uint32_t)((wc * 64 + b_nin) * 64);

    float acc[2][8][4];
    #pragma unroll
    for (int mf = 0; mf < 2; mf++)
        #pragma unroll
        for (int nf = 0; nf < 8; nf++)
            #pragma unroll
            for (int q = 0; q < 4; q++) acc[mf][nf][q] = 0.f;

    float rs[4];
    #pragma unroll
    for (int i = 0; i < 4; i++) rs[i] = 0.f;
    float4 v[4];

    #define AGGR_CPB(c) do { \
        uint32_t _st = sb + 32768u + (uint32_t)(((c) & 3) * 16384); \
        _Pragma("unroll") \
        for (int _it = 0; _it < 2; _it++) { \
            uint32_t _dst = _st + cpd + (uint32_t)(_it * 4096); \
            CP_ASYNC16(_dst,         cpsh + (long)_it * 64 * NN + (c) * 32); \
            CP_ASYNC16(_dst + 8192u, cpsl + (long)_it * 64 * NN + (c) * 32); \
        } \
        CP_COMMIT(); \
    } while (0)

    #define AGGR_LOADE(c) do { \
        _Pragma("unroll") \
        for (int _it = 0; _it < 4; _it++) \
            v[_it] = *(const float4*)(eP + (long)_it * 32 * NN + (c) * 32); \
    } while (0)

    #define AGGR_STOREE(c) do { \
        uint32_t _soff = (uint32_t)(((c) & 1) * 16384) + sA_off; \
        int _jb = (c) * 32 + e_cu * 4; \
        _Pragma("unroll") \
        for (int _it = 0; _it < 4; _it++) { \
            int _irow = i0 + e_row + _it * 32; \
            float4 _a = v[_it]; \
            if (_jb + 0 == _irow) _a.x = 0.f; \
            if (_jb + 1 == _irow) _a.y = 0.f; \
            if (_jb + 2 == _irow) _a.z = 0.f; \
            if (_jb + 3 == _irow) _a.w = 0.f; \
            rs[_it] += _a.x + _a.y + _a.z + _a.w; \
            uint32_t _h0 = prmt_hi(__float_as_uint(_a.x), __float_as_uint(_a.y)); \
            uint32_t _h1 = prmt_hi(__float_as_uint(_a.z), __float_as_uint(_a.w)); \
            uint32_t _l0 = cvt_bf16x2(_a.x - trunc_bf(_a.x), _a.y - trunc_bf(_a.y)); \
            uint32_t _l1 = cvt_bf16x2(_a.z - trunc_bf(_a.z), _a.w - trunc_bf(_a.w)); \
            uint32_t _off = _soff + (uint32_t)(_it * 2048); \
            *(uint2*)(dsm + _off)        = make_uint2(_h0, _h1); \
            *(uint2*)(dsm + 8192 + _off) = make_uint2(_l0, _l1); \
        } \
    } while (0)

    // prologue
    AGGR_CPB(0); AGGR_CPB(1); AGGR_CPB(2);
    AGGR_LOADE(0);
    AGGR_STOREE(0);
    AGGR_LOADE(1);

    #pragma unroll 4
    for (int c = 0; c < 16; c++) {
        if (c < 14) { CP_WAIT2(); } else if (c == 14) { CP_WAIT1(); } else { CP_WAIT0(); }
        __syncthreads();
        if (c < 13) AGGR_CPB(c + 3);
        if (c < 15) AGGR_STOREE(c + 1);
        if (c < 14) AGGR_LOADE(c + 2);
        uint32_t aHi = sb + (uint32_t)((c & 1) * 16384) + aRow;
        uint32_t bHi = sb + 32768u + (uint32_t)((c & 3) * 16384) + bRow;
        consume32(aHi, bHi, a_kb, a_xm, b_kb, b_xm, acc);
    }

    // rowsum reduce: 8 consecutive threads share a row
    __syncthreads();
    float* srs = (float*)(dsm + AG_SRS);
    #pragma unroll
    for (int it = 0; it < 4; it++) {
        float s = rs[it];
        #pragma unroll
        for (int m = 1; m <= 4; m <<= 1) s += __shfl_xor_sync(0xffffffffu, s, m);
        if ((lane & 7) == 0) srs[(tid >> 3) + it * 32] = s;
    }
    __syncthreads();
    float* rinv = (float*)(dsm + AG_SRINV);
    if (tid < 128) rinv[tid] = 1.f / fmaxf(srs[tid], 1e-12f);
    __syncthreads();

    // epilogue: scale + split bf16 store
    #pragma unroll
    for (int mf = 0; mf < 2; mf++) {
        const int lr0 = wr * 32 + mf * 16 + (lane >> 2);
        const float inv0 = rinv[lr0], inv1 = rinv[lr0 + 8];
        long idx0 = ((long)(b * NN + i0 + lr0)) * C1 + edge * 128 + wc * 64 + 2 * (lane & 3);
        long idx1 = idx0 + 8L * C1;
        #pragma unroll
        for (int nf = 0; nf < 8; nf++) {
            float x0 = acc[mf][nf][0] * inv0, x1 = acc[mf][nf][1] * inv0;
            float y0 = acc[mf][nf][2] * inv1, y1 = acc[mf][nf][3] * inv1;
            *(uint32_t*)(g_xh + idx0 + nf * 8) = prmt_hi(__float_as_uint(x0), __float_as_uint(x1));
            *(uint32_t*)(g_xl + idx0 + nf * 8) = cvt_bf16x2(x0 - trunc_bf(x0), x1 - trunc_bf(x1));
            *(uint32_t*)(g_xh + idx1 + nf * 8) = prmt_hi(__float_as_uint(y0), __float_as_uint(y1));
            *(uint32_t*)(g_xl + idx1 + nf * 8) = cvt_bf16x2(y0 - trunc_bf(y0), y1 - trunc_bf(y1));
        }
    }
}

// ---------------------------------------------------------------------------
// K2: HMMA gemm1 (3-stage all-cp.async pipeline, K=32 x8 chunks) + BN stats
// ---------------------------------------------------------------------------
__global__ __launch_bounds__(256, 2) void k_gemm1h() {
    const uint32_t sb = smem_u32(dsm);
    const int tid = threadIdx.x;
    const int lane = tid & 31, wid = tid >> 5;
    const int wr = wid >> 1, wc = wid & 1;
    const long m0 = (long)blockIdx.y * 128;
    const int n0 = blockIdx.x * 128;

    const int g_r = tid >> 2, g_u = tid & 3;
    const __nv_bfloat16* sxh = g_xh + (m0 + g_r) * C1 + g_u * 8;
    const __nv_bfloat16* sxl = g_xl + (m0 + g_r) * C1 + g_u * 8;
    const __nv_bfloat16* swh = g_w1h + (long)(n0 + g_r) * C1 + g_u * 8;
    const __nv_bfloat16* swl = g_w1l + (long)(n0 + g_r) * C1 + g_u * 8;
    const uint32_t cpd = (uint32_t)(g_r * 64) + SW64R(g_r, g_u * 16);

    const int a_rin = (lane & 7) + ((lane >> 3) & 1) * 8;
    const int a_kb  = (lane >> 4) * 16;
    const int a_row = wr * 32 + a_rin;
    const uint32_t a_xm = (((uint32_t)a_rin >> 1) & 3u) << 4;
    const uint32_t aRow = (uint32_t)(a_row * 64);
    const int b_nin = (lane & 7) + (lane >= 16 ? 8 : 0);
    const int b_kb  = ((lane >> 3) & 1) * 16;
    const uint32_t b_xm = (((uint32_t)b_nin >> 1) & 3u) << 4;
    const uint32_t bRow = (uint32_t)((wc * 64 + b_nin) * 64);

    float* ssum = (float*)(dsm + SG_SUM);
    float* ssq  = (float*)(dsm + SG_SQ);
    if (tid < 128) { ssum[tid] = 0.f; ssq[tid] = 0.f; }

    float acc[2][8][4];
    #pragma unroll
    for (int mf = 0; mf < 2; mf++)
        #pragma unroll
        for (int nf = 0; nf < 8; nf++)
            #pragma unroll
            for (int q = 0; q < 4; q++) acc[mf][nf][q] = 0.f;

    #define G1_CP(c) do { \
        uint32_t _st = sb + (uint32_t)(((c) % 3) * 32768); \
        _Pragma("unroll") \
        for (int _it = 0; _it < 2; _it++) { \
            uint32_t _dst = _st + cpd + (uint32_t)(_it * 4096); \
            CP_ASYNC16(_dst,          sxh + (long)_it * 64 * C1 + (c) * 32); \
            CP_ASYNC16(_dst + 8192u,  sxl + (long)_it * 64 * C1 + (c) * 32); \
            CP_ASYNC16(_dst + 16384u, swh + (long)_it * 64 * C1 + (c) * 32); \
            CP_ASYNC16(_dst + 24576u, swl + (long)_it * 64 * C1 + (c) * 32); \
        } \
        CP_COMMIT(); \
    } while (0)

    G1_CP(0);
    G1_CP(1);
    #pragma unroll
    for (int c = 0; c < 8; c++) {
        if (c < 7) { CP_WAIT1(); } else { CP_WAIT0(); }
        __syncthreads();
        if (c < 6) G1_CP(c + 2);
        uint32_t st = sb + (uint32_t)((c % 3) * 32768);
        consume32(st + aRow, st + 16384u + bRow, a_kb, a_xm, b_kb, b_xm, acc);
    }

    // store h1 + stats
    #pragma unroll
    for (int mf = 0; mf < 2; mf++) {
        const int lr0 = wr * 32 + mf * 16 + (lane >> 2);
        float* d0 = g_h1 + (m0 + lr0) * C1 + n0 + wc * 64 + 2 * (lane & 3);
        float* d1 = d0 + 8L * C1;
        #pragma unroll
        for (int nf = 0; nf < 8; nf++) {
            *(float2*)(d0 + nf * 8) = make_float2(acc[mf][nf][0], acc[mf][nf][1]);
            *(float2*)(d1 + nf * 8) = make_float2(acc[mf][nf][2], acc[mf][nf][3]);
        }
    }
    #pragma unroll
    for (int nf = 0; nf < 8; nf++) {
        #pragma unroll
        for (int par = 0; par < 2; par++) {
            float v0 = acc[0][nf][par], v1 = acc[0][nf][par + 2];
            float v2 = acc[1][nf][par], v3 = acc[1][nf][par + 2];
            float s = v0 + v1 + v2 + v3;
            float q = v0 * v0 + v1 * v1 + v2 * v2 + v3 * v3;
            #pragma unroll
            for (int m = 4; m <= 16; m <<= 1) {
                s += __shfl_xor_sync(0xffffffffu, s, m);
                q += __shfl_xor_sync(0xffffffffu, q, m);
            }
            if (lane < 4) {
                int ch = wc * 64 + nf * 8 + 2 * lane + par;
                atomicAdd(&ssum[ch], s);
                atomicAdd(&ssq[ch], q);
            }
        }
    }
    __syncthreads();
    if (tid < 128) {
        atomicAdd(&g_stats[n0 + tid], ssum[tid]);
        atomicAdd(&g_stats[256 + n0 + tid], ssq[tid]);
    }
}

// ---------------------------------------------------------------------------
__global__ void k_bnaff(const float* __restrict__ g, const float* __restrict__ b,
                        int C, int statoff, int affoff) {
    int o = threadIdx.x;
    if (o < C) {
        const float inv_cnt = 1.f / 131072.f;
        float mean = g_stats[statoff + o] * inv_cnt;
        float var  = g_stats[statoff + C + o] * inv_cnt - mean * mean;
        float sc = g[o] * rsqrtf(var + 1e-5f);
        g_aff[affoff + o]     = sc;
        g_aff[affoff + C + o] = b[o] - mean * sc;
    }
}

// ---------------------------------------------------------------------------
// K4: HMMA gemm2 (A 2-stage affine+split, B 4-stage cp.async, K=32 x8)
//  Body: wait -> sync -> cp(c+3) -> storeA(c+1) -> loadA(c+2) -> consume(c)
// ---------------------------------------------------------------------------
__global__ __launch_bounds__(256, 2) void k_gemm2h() {
    const uint32_t sb = smem_u32(dsm);
    const int tid = threadIdx.x;
    const int lane = tid & 31, wid = tid >> 5;
    const int wr = wid >> 1, wc = wid & 1;
    const long m0 = (long)blockIdx.x * 128;

    const int e_row = tid >> 3, e_cu = tid & 7;
    const float* aP = g_h1 + (m0 + e_row) * C1 + e_cu * 4;
    const uint32_t sA_off = (uint32_t)(e_row * 64) + SW64R(e_row, (e_cu >> 1) * 16)
                          + (uint32_t)((e_cu & 1) * 8);
    const int b_d = tid >> 2, b_u = tid & 3;
    const __nv_bfloat16* cpsh = g_w2h + (long)b_d * C1 + b_u * 8;
    const __nv_bfloat16* cpsl = g_w2l + (long)b_d * C1 + b_u * 8;
    const uint32_t cpd = (uint32_t)(b_d * 64) + SW64R(b_d, b_u * 16);

    const int a_rin = (lane & 7) + ((lane >> 3) & 1) * 8;
    const int a_kb  = (lane >> 4) * 16;
    const int a_row = wr * 32 + a_rin;
    const uint32_t a_xm = (((uint32_t)a_rin >> 1) & 3u) << 4;
    const uint32_t aRow = (uint32_t)(a_row * 64);
    const int b_nin = (lane & 7) + (lane >= 16 ? 8 : 0);
    const int b_kb  = ((lane >> 3) & 1) * 16;
    const uint32_t b_xm = (((uint32_t)b_nin >> 1) & 3u) << 4;
    const uint32_t bRow = (uint32_t)((wc * 64 + b_nin) * 64);

    float* saff0 = (float*)(dsm + S2_AFF);
    float* saff1 = saff0 + 256;
    float* ssum  = (float*)(dsm + S2_SUM);
    float* ssq   = (float*)(dsm + S2_SQ);
    saff0[tid] = g_aff[tid];
    saff1[tid] = g_aff[256 + tid];
    if (tid < 128) { ssum[tid] = 0.f; ssq[tid] = 0.f; }
    __syncthreads();

    float acc[2][8][4];
    #pragma unroll
    for (int mf = 0; mf < 2; mf++)
        #pragma unroll
        for (int nf = 0; nf < 8; nf++)
            #pragma unroll
            for (int q = 0; q < 4; q++) acc[mf][nf][q] = 0.f;

    float4 v[4];

    #define G2_CPB(c) do { \
        uint32_t _st = sb + 32768u + (uint32_t)(((c) & 3) * 16384); \
        _Pragma("unroll") \
        for (int _it = 0; _it < 2; _it++) { \
            uint32_t _dst = _st + cpd + (uint32_t)(_it * 4096); \
            CP_ASYNC16(_dst,         cpsh + (long)_it * 64 * C1 + (c) * 32); \
            CP_ASYNC16(_dst + 8192u, cpsl + (long)_it * 64 * C1 + (c) * 32); \
        } \
        CP_COMMIT(); \
    } while (0)

    #define G2_LOADA(c) do { \
        _Pragma("unroll") \
        for (int _it = 0; _it < 4; _it++) \
            v[_it] = *(const float4*)(aP + (long)_it * 32 * C1 + (c) * 32); \
    } while (0)

    #define G2_STOREA(c) do { \
        uint32_t _soff = (uint32_t)(((c) & 1) * 16384) + sA_off; \
        int _ch = (c) * 32 + e_cu * 4; \
        _Pragma("unroll") \
        for (int _it = 0; _it < 4; _it++) { \
            float4 _a = v[_it]; \
            _a.x = lrelu(saff0[_ch + 0] * _a.x + saff1[_ch + 0]); \
            _a.y = lrelu(saff0[_ch + 1] * _a.y + saff1[_ch + 1]); \
            _a.z = lrelu(saff0[_ch + 2] * _a.z + saff1[_ch + 2]); \
            _a.w = lrelu(saff0[_ch + 3] * _a.w + saff1[_ch + 3]); \
            uint32_t _h0 = prmt_hi(__float_as_uint(_a.x), __float_as_uint(_a.y)); \
            uint32_t _h1 = prmt_hi(__float_as_uint(_a.z), __float_as_uint(_a.w)); \
            uint32_t _l0 = cvt_bf16x2(_a.x - trunc_bf(_a.x), _a.y - trunc_bf(_a.y)); \
            uint32_t _l1 = cvt_bf16x2(_a.z - trunc_bf(_a.z), _a.w - trunc_bf(_a.w)); \
            uint32_t _off = _soff + (uint32_t)(_it * 2048); \
            *(uint2*)(dsm + _off)        = make_uint2(_h0, _h1); \
            *(uint2*)(dsm + 8192 + _off) = make_uint2(_l0, _l1); \
        } \
    } while (0)

    G2_CPB(0); G2_CPB(1); G2_CPB(2);
    G2_LOADA(0);
    G2_STOREA(0);
    G2_LOADA(1);

    #pragma unroll
    for (int c = 0; c < 8; c++) {
        if (c < 6) { CP_WAIT2(); } else if (c == 6) { CP_WAIT1(); } else { CP_WAIT0(); }
        __syncthreads();
        if (c < 5) G2_CPB(c + 3);
        if (c < 7) G2_STOREA(c + 1);
        if (c < 6) G2_LOADA(c + 2);
        uint32_t aHi = sb + (uint32_t)((c & 1) * 16384) + aRow;
        uint32_t bHi = sb + 32768u + (uint32_t)((c & 3) * 16384) + bRow;
        consume32(aHi, bHi, a_kb, a_xm, b_kb, b_xm, acc);
    }

    // store h2 + stats
    #pragma unroll
    for (int mf = 0; mf < 2; mf++) {
        const int lr0 = wr * 32 + mf * 16 + (lane >> 2);
        float* d0 = g_h2 + (m0 + lr0) * C2 + wc * 64 + 2 * (lane & 3);
        float* d1 = d0 + 8L * C2;
        #pragma unroll
        for (int nf = 0; nf < 8; nf++) {
            *(float2*)(d0 + nf * 8) = make_float2(acc[mf][nf][0], acc[mf][nf][1]);
            *(float2*)(d1 + nf * 8) = make_float2(acc[mf][nf][2], acc[mf][nf][3]);
        }
    }
    #pragma unroll
    for (int nf = 0; nf < 8; nf++) {
        #pragma unroll
        for (int par = 0; par < 2; par++) {
            float v0 = acc[0][nf][par], v1 = acc[0][nf][par + 2];
            float v2 = acc[1][nf][par], v3 = acc[1][nf][par + 2];
            float s = v0 + v1 + v2 + v3;
            float q = v0 * v0 + v1 * v1 + v2 * v2 + v3 * v3;
            #pragma unroll
            for (int m = 4; m <= 16; m <<= 1) {
                s += __shfl_xor_sync(0xffffffffu, s, m);
                q += __shfl_xor_sync(0xffffffffu, q, m);
            }
            if (lane < 4) {
                int ch = wc * 64 + nf * 8 + 2 * lane + par;
                atomicAdd(&ssum[ch], s);
                atomicAdd(&ssq[ch], q);
            }
        }
    }
    __syncthreads();
    if (tid < 128) {
        atomicAdd(&g_stats[512 + tid], ssum[tid]);
        atomicAdd(&g_stats[640 + tid], ssq[tid]);
    }
}

// ---------------------------------------------------------------------------
__global__ __launch_bounds__(256) void k_final(float* __restrict__ out) {
    long idx = ((long)blockIdx.x * blockDim.x + threadIdx.x);
    long e = idx * 4;
    int ch = (int)(e & 127);
    float4 v = *(const float4*)&g_h2[e];
    v.x = lrelu(g_aff[512 + ch + 0] * v.x + g_aff[640 + ch + 0]);
    v.y = lrelu(g_aff[512 + ch + 1] * v.y + g_aff[640 + ch + 1]);
    v.z = lrelu(g_aff[512 + ch + 2] * v.z + g_aff[640 + ch + 2]);
    v.w = lrelu(g_aff[512 + ch + 3] * v.w + g_aff[640 + ch + 3]);
    *(float4*)&out[e] = v;
}

// ---------------------------------------------------------------------------
extern "C" void kernel_launch(void* const* d_in, const int* in_sizes, int n_in,
                              void* d_out, int out_size) {
    const float* Ed = (const float*)d_in[0];
    const float* Ei = (const float*)d_in[1];
    const float* P  = (const float*)d_in[2];
    const float* W1 = (const float*)d_in[3];
    const float* g1 = (const float*)d_in[4];
    const float* b1 = (const float*)d_in[5];
    const float* W2 = (const float*)d_in[6];
    const float* g2 = (const float*)d_in[7];
    const float* b2 = (const float*)d_in[8];
    float* out = (float*)d_out;

    cudaFuncSetAttribute((const void*)k_aggr,
                         cudaFuncAttributeMaxDynamicSharedMemorySize, AG_TOT);
    cudaFuncSetAttribute((const void*)k_gemm1h,
                         cudaFuncAttributeMaxDynamicSharedMemorySize, SG_TOT);
    cudaFuncSetAttribute((const void*)k_gemm2h,
                         cudaFuncAttributeMaxDynamicSharedMemorySize, S2_TOT);

    k_init<<<16769, 256>>>(P, W1, W2);
    k_aggr<<<dim3(4, 256, 2), 256, AG_TOT>>>(Ed, Ei);
    k_gemm1h<<<dim3(2, 1024), 256, SG_TOT>>>();
    k_bnaff<<<1, 256>>>(g1, b1, 256, 0, 0);
    k_gemm2h<<<1024, 256, S2_TOT>>>();
    k_bnaff<<<1, 128>>>(g2, b2, 128, 512, 512);
    k_final<<<(int)(BN_ * C2 / 4 / 256), 256>>>(out);
}